// round 5
// baseline (speedup 1.0000x reference)
#include <cuda_runtime.h>
#include <math.h>

// ---------------- scratch (device globals; no allocation at launch) ----------------
#define NMAX 10000
#define EMAX 320000
#define ETMAX (EMAX + NMAX)

__device__ float g_h  [NMAX * 768];   // pre-aggregation features of current layer
__device__ float g_x1 [NMAX * 256];
__device__ float g_x2 [NMAX * 256];
__device__ float g_x3 [NMAX * 768];
__device__ float g_al [NMAX * 12];
__device__ float g_ar [NMAX * 12];
__device__ float g_e  [ETMAX * 12];   // per-slot, per-head scores -> exp (CSR order)
__device__ float g_mh1[NMAX * 128];
__device__ float g_mh2[NMAX * 64];
__device__ int   g_deg   [NMAX];
__device__ int   g_rowptr[NMAX + 1];
__device__ int   g_cursor[NMAX];
__device__ int   g_csrsrc[ETMAX];
__device__ int   g_csrdst[ETMAX];

__device__ __forceinline__ float sigmoidf_(float x) {
    return 1.f / (1.f + expf(-x));
}

static inline int cdiv(int a, int b) { return (a + b - 1) / b; }

// ---------------- CSR build ----------------
__global__ void zero_int(int* p, int n) {
    int t = blockIdx.x * blockDim.x + threadIdx.x;
    if (t < n) p[t] = 0;
}

__global__ void count_deg(const int* __restrict__ ei, int E, int Et, int* __restrict__ deg) {
    int e = blockIdx.x * blockDim.x + threadIdx.x;
    if (e >= Et) return;
    int d = (e < E) ? ei[E + e] : (e - E);
    atomicAdd(&deg[d], 1);
}

__global__ void scan_deg(const int* __restrict__ deg, int* __restrict__ rowptr,
                         int* __restrict__ cursor, int Nn) {
    __shared__ int part[256];
    __shared__ int partx[256];
    int chunk = (Nn + 255) / 256;
    int begin = threadIdx.x * chunk;
    int end = begin + chunk; if (end > Nn) end = Nn;
    if (begin > Nn) begin = Nn;
    int s = 0;
    for (int i = begin; i < end; ++i) s += deg[i];
    part[threadIdx.x] = s;
    __syncthreads();
    if (threadIdx.x == 0) {
        int run = 0;
        for (int i = 0; i < 256; ++i) { partx[i] = run; run += part[i]; }
    }
    __syncthreads();
    int run = partx[threadIdx.x];
    for (int i = begin; i < end; ++i) {
        rowptr[i] = run; cursor[i] = run;
        run += deg[i];
    }
    if (end == Nn && begin <= Nn) rowptr[Nn] = run;
}

__global__ void scatter_csr(const int* __restrict__ ei, int E, int Et,
                            int* __restrict__ cursor, int* __restrict__ csr_src,
                            int* __restrict__ csr_dst) {
    int e = blockIdx.x * blockDim.x + threadIdx.x;
    if (e >= Et) return;
    int s, d;
    if (e < E) { s = ei[e]; d = ei[E + e]; }
    else       { s = e - E; d = e - E; }
    int pos = atomicAdd(&cursor[d], 1);
    csr_src[pos] = s;
    csr_dst[pos] = d;
}

// ---------------- tiled SGEMM: C[M,N] = A[M,K] @ B[K,N] ----------------
// 128x128 tile, BK=8, 256 threads, 8x8 per thread. N mult of 128, K mult of 8.
__global__ void __launch_bounds__(256, 2)
sgemm128(const float* __restrict__ A, const float* __restrict__ B,
         float* __restrict__ Cmat, int M, int N, int K) {
    __shared__ float As[8][128];
    __shared__ float Bs[8][132];
    int t = threadIdx.x;
    int row0 = blockIdx.x * 128;
    int col0 = blockIdx.y * 128;
    int ar = t >> 1, ac = (t & 1) * 4;    // A-load: 128 rows x 8 k
    int br = t >> 5, bc = (t & 31) * 4;   // B-load: 8 k x 128 cols
    int tx = t & 15, ty = t >> 4;

    float acc[8][8];
#pragma unroll
    for (int i = 0; i < 8; ++i)
#pragma unroll
        for (int j = 0; j < 8; ++j) acc[i][j] = 0.f;

    for (int k0 = 0; k0 < K; k0 += 8) {
        float4 av = make_float4(0.f, 0.f, 0.f, 0.f);
        if (row0 + ar < M)
            av = *(const float4*)(A + (size_t)(row0 + ar) * K + k0 + ac);
        As[ac + 0][ar] = av.x;
        As[ac + 1][ar] = av.y;
        As[ac + 2][ar] = av.z;
        As[ac + 3][ar] = av.w;
        *(float4*)&Bs[br][bc] = *(const float4*)(B + (size_t)(k0 + br) * N + col0 + bc);
        __syncthreads();
#pragma unroll
        for (int k = 0; k < 8; ++k) {
            float4 a0 = *(const float4*)&As[k][ty * 8];
            float4 a1 = *(const float4*)&As[k][ty * 8 + 4];
            float4 b0 = *(const float4*)&Bs[k][tx * 8];
            float4 b1 = *(const float4*)&Bs[k][tx * 8 + 4];
            float aa[8] = {a0.x, a0.y, a0.z, a0.w, a1.x, a1.y, a1.z, a1.w};
            float bb[8] = {b0.x, b0.y, b0.z, b0.w, b1.x, b1.y, b1.z, b1.w};
#pragma unroll
            for (int i = 0; i < 8; ++i)
#pragma unroll
                for (int j = 0; j < 8; ++j)
                    acc[i][j] += aa[i] * bb[j];
        }
        __syncthreads();
    }
#pragma unroll
    for (int i = 0; i < 8; ++i) {
        int r = row0 + ty * 8 + i;
        if (r < M) {
            float4 v0 = make_float4(acc[i][0], acc[i][1], acc[i][2], acc[i][3]);
            float4 v1 = make_float4(acc[i][4], acc[i][5], acc[i][6], acc[i][7]);
            float* cp = Cmat + (size_t)r * N + col0 + tx * 8;
            *(float4*)cp = v0;
            *(float4*)(cp + 4) = v1;
        }
    }
}

// ---------------- per-node attention scores al/ar ----------------
__global__ void alar_kernel(const float* __restrict__ Hmat,
                            const float* __restrict__ a_s, const float* __restrict__ a_d,
                            float* __restrict__ al, float* __restrict__ ar,
                            int Nn, int H, int C) {
    int t = blockIdx.x * blockDim.x + threadIdx.x;
    if (t >= Nn * H) return;
    int n = t / H, h = t - n * H;
    const float* hp = Hmat + (size_t)n * H * C + h * C;
    float sa = 0.f, sd = 0.f;
    for (int c = 0; c < C; ++c) {
        float v = hp[c];
        sa += v * a_s[h * C + c];
        sd += v * a_d[h * C + c];
    }
    al[t] = sa;
    ar[t] = sd;
}

// ---------------- per-slot scores for all heads (CSR order) ----------------
template<int H>
__global__ void edge_score_csr(const int* __restrict__ csr_src, const int* __restrict__ csr_dst,
                               int Et,
                               const float* __restrict__ al, const float* __restrict__ ar,
                               float* __restrict__ ebuf) {
    int i = blockIdx.x * blockDim.x + threadIdx.x;
    if (i >= Et) return;
    int s = csr_src[i];
    int d = csr_dst[i];
    const float4* a4 = (const float4*)(al + s * H);
    const float4* r4 = (const float4*)(ar + d * H);
    float4* o4 = (float4*)(ebuf + (size_t)i * H);
#pragma unroll
    for (int q = 0; q < H / 4; ++q) {
        float4 a = a4[q], r = r4[q];
        float4 v;
        v.x = a.x + r.x; v.x = v.x > 0.f ? v.x : 0.2f * v.x;
        v.y = a.y + r.y; v.y = v.y > 0.f ? v.y : 0.2f * v.y;
        v.z = a.z + r.z; v.z = v.z > 0.f ? v.z : 0.2f * v.z;
        v.w = a.w + r.w; v.w = v.w > 0.f ? v.w : 0.2f * v.w;
        o4[q] = v;
    }
}

// ---------------- block-per-node aggregation: H warps (one per head) ----------------
// pass 2 overwrites ebuf with exp(e - m); pass 3 only multiplies.
template<int H, int C_>
__global__ void agg_node(const int* __restrict__ rowptr, const int* __restrict__ csr_src,
                         float* __restrict__ ebuf, const float* __restrict__ Hmat,
                         const float* __restrict__ bias, float* __restrict__ Out, int Nn) {
    int n = blockIdx.x;
    int h = threadIdx.x >> 5;
    int lane = threadIdx.x & 31;
    const int HC = H * C_;
    int rs = rowptr[n], re = rowptr[n + 1];

    // pass 1: max (lane-parallel over edges)
    float m = -INFINITY;
    for (int i = rs + lane; i < re; i += 32)
        m = fmaxf(m, ebuf[(size_t)i * H + h]);
#pragma unroll
    for (int o = 16; o; o >>= 1) m = fmaxf(m, __shfl_xor_sync(0xffffffffu, m, o));

    // pass 2: exp in place + sum
    float ssum = 0.f;
    for (int i = rs + lane; i < re; i += 32) {
        float ex = __expf(ebuf[(size_t)i * H + h] - m);
        ebuf[(size_t)i * H + h] = ex;
        ssum += ex;
    }
#pragma unroll
    for (int o = 16; o; o >>= 1) ssum += __shfl_xor_sync(0xffffffffu, ssum, o);
    float inv_s = 1.f / ssum;

    // pass 3: serial accumulate (channel-parallel across lanes)
    float acc0 = 0.f, acc1 = 0.f;
#pragma unroll 2
    for (int i = rs; i < re; ++i) {
        int s = csr_src[i];                              // broadcast
        float a = ebuf[(size_t)i * H + h] * inv_s;       // broadcast
        const float* hp = Hmat + (size_t)s * HC + h * C_;
        acc0 += a * hp[lane];
        if (C_ == 64) acc1 += a * hp[lane + 32];
    }
    float* op = Out + (size_t)n * HC + h * C_;
    float v0 = acc0 + bias[h * C_ + lane];
    op[lane] = v0 > 0.f ? v0 : 0.f;
    if (C_ == 64) {
        float v1 = acc1 + bias[h * C_ + lane + 32];
        op[lane + 32] = v1 > 0.f ? v1 : 0.f;
    }
}

// ---------------- final head: out1 = sigmoid(concat(x1,x2,x3) @ Wf + bf) ----------------
__global__ void final_head(const float* __restrict__ x1, const float* __restrict__ x2,
                           const float* __restrict__ x3, const float* __restrict__ Wf,
                           const float* __restrict__ bf, float* __restrict__ out1, int Nn) {
    int warp = (blockIdx.x * blockDim.x + threadIdx.x) >> 5;
    int lane = threadIdx.x & 31;
    if (warp >= Nn) return;
    float acc = 0.f;
    for (int j = lane; j < 256; j += 32) acc += x1[(size_t)warp * 256 + j] * Wf[j];
    for (int j = lane; j < 256; j += 32) acc += x2[(size_t)warp * 256 + j] * Wf[256 + j];
    for (int j = lane; j < 768; j += 32) acc += x3[(size_t)warp * 768 + j] * Wf[512 + j];
#pragma unroll
    for (int o = 16; o; o >>= 1) acc += __shfl_down_sync(0xffffffffu, acc, o);
    if (lane == 0) out1[warp] = sigmoidf_(acc + bf[0]);
}

// ---------------- MLP ----------------
__global__ void mlp1(const float* __restrict__ x, const float* __restrict__ out1,
                     const float* __restrict__ M1w, const float* __restrict__ M1b,
                     float* __restrict__ h1, int Nn) {
    int t = blockIdx.x * blockDim.x + threadIdx.x;
    if (t >= Nn * 128) return;
    int n = t / 128, j = t - n * 128;
    float acc = M1b[j];
    const float* xr = x + n * 16;
#pragma unroll
    for (int k = 0; k < 16; ++k) acc += xr[k] * M1w[k * 128 + j];
    acc += out1[n] * M1w[16 * 128 + j];
    h1[t] = acc > 0.f ? acc : 0.f;
}

__global__ void mlp2(const float* __restrict__ h1, const float* __restrict__ M2w,
                     const float* __restrict__ M2b, float* __restrict__ h2, int Nn) {
    int t = blockIdx.x * blockDim.x + threadIdx.x;
    if (t >= Nn * 64) return;
    int n = t / 64, j = t - n * 64;
    float acc = M2b[j];
    const float* hr = h1 + (size_t)n * 128;
    for (int k = 0; k < 128; ++k) acc += hr[k] * M2w[k * 64 + j];
    h2[t] = acc > 0.f ? acc : 0.f;
}

__global__ void mlp3(const float* __restrict__ h2, const float* __restrict__ M3w,
                     const float* __restrict__ M3b, float* __restrict__ out2, int Nn) {
    int warp = (blockIdx.x * blockDim.x + threadIdx.x) >> 5;
    int lane = threadIdx.x & 31;
    if (warp >= Nn) return;
    float acc = h2[(size_t)warp * 64 + lane] * M3w[lane]
              + h2[(size_t)warp * 64 + lane + 32] * M3w[lane + 32];
#pragma unroll
    for (int o = 16; o; o >>= 1) acc += __shfl_down_sync(0xffffffffu, acc, o);
    if (lane == 0) out2[warp] = sigmoidf_(acc + M3b[0]);
}

// ---------------- host orchestration ----------------
static void run_gat_layer(const float* X, int K,
                          const float* W, const float* a_s, const float* a_d, const float* b,
                          int H, int C, int Nn, int Et,
                          const int* rowptr, const int* csrsrc, const int* csrdst,
                          float* hbuf, float* albuf, float* arbuf, float* ebuf,
                          float* Out) {
    int HC = H * C;
    dim3 gg(cdiv(Nn, 128), HC / 128);
    sgemm128<<<gg, 256>>>(X, W, hbuf, Nn, HC, K);
    alar_kernel<<<cdiv(Nn * H, 256), 256>>>(hbuf, a_s, a_d, albuf, arbuf, Nn, H, C);
    if (H == 8) {
        edge_score_csr<8><<<cdiv(Et, 256), 256>>>(csrsrc, csrdst, Et, albuf, arbuf, ebuf);
        agg_node<8, 32><<<Nn, 256>>>(rowptr, csrsrc, ebuf, hbuf, b, Out, Nn);
    } else {
        edge_score_csr<12><<<cdiv(Et, 256), 256>>>(csrsrc, csrdst, Et, albuf, arbuf, ebuf);
        agg_node<12, 64><<<Nn, 384>>>(rowptr, csrsrc, ebuf, hbuf, b, Out, Nn);
    }
}

extern "C" void kernel_launch(void* const* d_in, const int* in_sizes, int n_in,
                              void* d_out, int out_size) {
    const float* x   = (const float*)d_in[0];
    const int*   ei  = (const int*)  d_in[1];
    const float* W1  = (const float*)d_in[3];
    const float* a1s = (const float*)d_in[4];
    const float* a1d = (const float*)d_in[5];
    const float* b1  = (const float*)d_in[6];
    const float* W2  = (const float*)d_in[7];
    const float* a2s = (const float*)d_in[8];
    const float* a2d = (const float*)d_in[9];
    const float* b2  = (const float*)d_in[10];
    const float* W3  = (const float*)d_in[11];
    const float* a3s = (const float*)d_in[12];
    const float* a3d = (const float*)d_in[13];
    const float* b3  = (const float*)d_in[14];
    const float* Wf  = (const float*)d_in[15];
    const float* bf  = (const float*)d_in[16];
    const float* M1w = (const float*)d_in[17];
    const float* M1b = (const float*)d_in[18];
    const float* M2w = (const float*)d_in[19];
    const float* M2b = (const float*)d_in[20];
    const float* M3w = (const float*)d_in[21];
    const float* M3b = (const float*)d_in[22];

    int Nn = in_sizes[0] / 16;
    int E  = in_sizes[1] / 2;
    int Et = E + Nn;

    float *h_, *x1_, *x2_, *x3_, *al_, *ar_, *e_, *mh1_, *mh2_;
    int *deg_, *rowptr_, *cursor_, *csrsrc_, *csrdst_;
    cudaGetSymbolAddress((void**)&h_,     g_h);
    cudaGetSymbolAddress((void**)&x1_,    g_x1);
    cudaGetSymbolAddress((void**)&x2_,    g_x2);
    cudaGetSymbolAddress((void**)&x3_,    g_x3);
    cudaGetSymbolAddress((void**)&al_,    g_al);
    cudaGetSymbolAddress((void**)&ar_,    g_ar);
    cudaGetSymbolAddress((void**)&e_,     g_e);
    cudaGetSymbolAddress((void**)&mh1_,   g_mh1);
    cudaGetSymbolAddress((void**)&mh2_,   g_mh2);
    cudaGetSymbolAddress((void**)&deg_,   g_deg);
    cudaGetSymbolAddress((void**)&rowptr_,g_rowptr);
    cudaGetSymbolAddress((void**)&cursor_,g_cursor);
    cudaGetSymbolAddress((void**)&csrsrc_,g_csrsrc);
    cudaGetSymbolAddress((void**)&csrdst_,g_csrdst);

    float* out1 = (float*)d_out;        // [N]
    float* out2 = (float*)d_out + Nn;   // [N]

    // ---- build CSR by destination (graph fixed across layers) ----
    zero_int<<<cdiv(Nn, 256), 256>>>(deg_, Nn);
    count_deg<<<cdiv(Et, 256), 256>>>(ei, E, Et, deg_);
    scan_deg<<<1, 256>>>(deg_, rowptr_, cursor_, Nn);
    scatter_csr<<<cdiv(Et, 256), 256>>>(ei, E, Et, cursor_, csrsrc_, csrdst_);

    // ---- GAT layers ----
    run_gat_layer(x,   16,  W1, a1s, a1d, b1, 8, 32,  Nn, Et,
                  rowptr_, csrsrc_, csrdst_, h_, al_, ar_, e_, x1_);
    run_gat_layer(x1_, 256, W2, a2s, a2d, b2, 8, 32,  Nn, Et,
                  rowptr_, csrsrc_, csrdst_, h_, al_, ar_, e_, x2_);
    run_gat_layer(x2_, 256, W3, a3s, a3d, b3, 12, 64, Nn, Et,
                  rowptr_, csrsrc_, csrdst_, h_, al_, ar_, e_, x3_);

    // ---- head ----
    final_head<<<cdiv(Nn * 32, 256), 256>>>(x1_, x2_, x3_, Wf, bf, out1, Nn);

    // ---- MLP ----
    mlp1<<<cdiv(Nn * 128, 256), 256>>>(x, out1, M1w, M1b, mh1_, Nn);
    mlp2<<<cdiv(Nn * 64, 256), 256>>>(mh1_, M2w, M2b, mh2_, Nn);
    mlp3<<<cdiv(Nn * 32, 256), 256>>>(mh2_, M3w, M3b, out2, Nn);
}

// round 6
// speedup vs baseline: 1.2243x; 1.2243x over previous
#include <cuda_runtime.h>
#include <math.h>

// ---------------- scratch (device globals; no allocation at launch) ----------------
#define NMAX 10000
#define EMAX 320000
#define ETMAX (EMAX + NMAX)

__device__ float g_h  [NMAX * 768];   // pre-aggregation features of current layer
__device__ float g_x1 [NMAX * 256];
__device__ float g_x2 [NMAX * 256];
__device__ float g_x3 [NMAX * 768];
__device__ float g_al [NMAX * 12];
__device__ float g_ar [NMAX * 12];
__device__ float g_e  [12 * ETMAX];   // HEAD-MAJOR: g_e[h*ETMAX + slot]
__device__ float g_mh1[NMAX * 128];
__device__ float g_mh2[NMAX * 64];
__device__ int   g_deg   [NMAX];
__device__ int   g_rowptr[NMAX + 1];
__device__ int   g_cursor[NMAX];
__device__ int   g_csrsrc[ETMAX];
__device__ int   g_csrdst[ETMAX];

__device__ __forceinline__ float sigmoidf_(float x) {
    return 1.f / (1.f + expf(-x));
}

static inline int cdiv(int a, int b) { return (a + b - 1) / b; }

// ---------------- CSR build ----------------
__global__ void zero_int(int* p, int n) {
    int t = blockIdx.x * blockDim.x + threadIdx.x;
    if (t < n) p[t] = 0;
}

__global__ void count_deg(const int* __restrict__ ei, int E, int Et, int* __restrict__ deg) {
    int e = blockIdx.x * blockDim.x + threadIdx.x;
    if (e >= Et) return;
    int d = (e < E) ? ei[E + e] : (e - E);
    atomicAdd(&deg[d], 1);
}

__global__ void scan_deg(const int* __restrict__ deg, int* __restrict__ rowptr,
                         int* __restrict__ cursor, int Nn) {
    __shared__ int part[256];
    __shared__ int partx[256];
    int chunk = (Nn + 255) / 256;
    int begin = threadIdx.x * chunk;
    int end = begin + chunk; if (end > Nn) end = Nn;
    if (begin > Nn) begin = Nn;
    int s = 0;
    for (int i = begin; i < end; ++i) s += deg[i];
    part[threadIdx.x] = s;
    __syncthreads();
    if (threadIdx.x == 0) {
        int run = 0;
        for (int i = 0; i < 256; ++i) { partx[i] = run; run += part[i]; }
    }
    __syncthreads();
    int run = partx[threadIdx.x];
    for (int i = begin; i < end; ++i) {
        rowptr[i] = run; cursor[i] = run;
        run += deg[i];
    }
    if (end == Nn && begin <= Nn) rowptr[Nn] = run;
}

__global__ void scatter_csr(const int* __restrict__ ei, int E, int Et,
                            int* __restrict__ cursor, int* __restrict__ csr_src,
                            int* __restrict__ csr_dst) {
    int e = blockIdx.x * blockDim.x + threadIdx.x;
    if (e >= Et) return;
    int s, d;
    if (e < E) { s = ei[e]; d = ei[E + e]; }
    else       { s = e - E; d = e - E; }
    int pos = atomicAdd(&cursor[d], 1);
    csr_src[pos] = s;
    csr_dst[pos] = d;
}

// ---------------- tiled SGEMM: C[M,N] = A[M,K] @ B[K,N] ----------------
// 64x64 tile, BK=16, 256 threads, 4x4 per thread. N, K multiples of (64, 16).
__global__ void sgemm64(const float* __restrict__ A, const float* __restrict__ B,
                        float* __restrict__ Cmat, int M, int N, int K) {
    __shared__ float As[16][68];   // transposed A tile, padded
    __shared__ float Bs[16][64];
    int t = threadIdx.x;
    int row0 = blockIdx.x * 64;
    int col0 = blockIdx.y * 64;
    int tx = t & 15, ty = t >> 4;
    int ar = t >> 2, ac = (t & 3) * 4;   // A-load coords (64 rows x 16 k)
    int br = t >> 4, bc = (t & 15) * 4;  // B-load coords (16 k x 64 cols)
    float acc[4][4];
#pragma unroll
    for (int i = 0; i < 4; ++i)
#pragma unroll
        for (int j = 0; j < 4; ++j) acc[i][j] = 0.f;

    for (int k0 = 0; k0 < K; k0 += 16) {
        float4 av = make_float4(0.f, 0.f, 0.f, 0.f);
        if (row0 + ar < M)
            av = *(const float4*)(A + (size_t)(row0 + ar) * K + k0 + ac);
        As[ac + 0][ar] = av.x;
        As[ac + 1][ar] = av.y;
        As[ac + 2][ar] = av.z;
        As[ac + 3][ar] = av.w;
        *(float4*)&Bs[br][bc] = *(const float4*)(B + (size_t)(k0 + br) * N + col0 + bc);
        __syncthreads();
#pragma unroll
        for (int k = 0; k < 16; ++k) {
            float4 a4 = *(const float4*)&As[k][ty * 4];
            float4 b4 = *(const float4*)&Bs[k][tx * 4];
            acc[0][0] += a4.x * b4.x; acc[0][1] += a4.x * b4.y;
            acc[0][2] += a4.x * b4.z; acc[0][3] += a4.x * b4.w;
            acc[1][0] += a4.y * b4.x; acc[1][1] += a4.y * b4.y;
            acc[1][2] += a4.y * b4.z; acc[1][3] += a4.y * b4.w;
            acc[2][0] += a4.z * b4.x; acc[2][1] += a4.z * b4.y;
            acc[2][2] += a4.z * b4.z; acc[2][3] += a4.z * b4.w;
            acc[3][0] += a4.w * b4.x; acc[3][1] += a4.w * b4.y;
            acc[3][2] += a4.w * b4.z; acc[3][3] += a4.w * b4.w;
        }
        __syncthreads();
    }
#pragma unroll
    for (int i = 0; i < 4; ++i) {
        int r = row0 + ty * 4 + i;
        if (r < M) {
            float4 v = make_float4(acc[i][0], acc[i][1], acc[i][2], acc[i][3]);
            *(float4*)(Cmat + (size_t)r * N + col0 + tx * 4) = v;
        }
    }
}

// ---------------- per-node attention scores al/ar ----------------
__global__ void alar_kernel(const float* __restrict__ Hmat,
                            const float* __restrict__ a_s, const float* __restrict__ a_d,
                            float* __restrict__ al, float* __restrict__ ar,
                            int Nn, int H, int C) {
    int t = blockIdx.x * blockDim.x + threadIdx.x;
    if (t >= Nn * H) return;
    int n = t / H, h = t - n * H;
    const float* hp = Hmat + (size_t)n * H * C + h * C;
    float sa = 0.f, sd = 0.f;
    for (int c = 0; c < C; ++c) {
        float v = hp[c];
        sa += v * a_s[h * C + c];
        sd += v * a_d[h * C + c];
    }
    al[t] = sa;
    ar[t] = sd;
}

// ---------------- per-slot scores for all heads (CSR order, HEAD-MAJOR out) ----------------
template<int H>
__global__ void edge_score_csr(const int* __restrict__ csr_src, const int* __restrict__ csr_dst,
                               int Et,
                               const float* __restrict__ al, const float* __restrict__ ar,
                               float* __restrict__ ebuf) {
    int i = blockIdx.x * blockDim.x + threadIdx.x;
    if (i >= Et) return;
    int s = csr_src[i];
    int d = csr_dst[i];
    const float4* a4 = (const float4*)(al + s * H);
    const float4* r4 = (const float4*)(ar + d * H);
#pragma unroll
    for (int q = 0; q < H / 4; ++q) {
        float4 a = a4[q], r = r4[q];
        float v0 = a.x + r.x; v0 = v0 > 0.f ? v0 : 0.2f * v0;
        float v1 = a.y + r.y; v1 = v1 > 0.f ? v1 : 0.2f * v1;
        float v2 = a.z + r.z; v2 = v2 > 0.f ? v2 : 0.2f * v2;
        float v3 = a.w + r.w; v3 = v3 > 0.f ? v3 : 0.2f * v3;
        ebuf[(size_t)(q * 4 + 0) * ETMAX + i] = v0;
        ebuf[(size_t)(q * 4 + 1) * ETMAX + i] = v1;
        ebuf[(size_t)(q * 4 + 2) * ETMAX + i] = v2;
        ebuf[(size_t)(q * 4 + 3) * ETMAX + i] = v3;
    }
}

// ---------------- block-per-node aggregation: H warps (one per head) ----------------
// ebuf is head-major [H][ETMAX]; pass 2 overwrites with exp(e - m) (coalesced).
template<int H, int C_>
__global__ void agg_node(const int* __restrict__ rowptr, const int* __restrict__ csr_src,
                         float* __restrict__ ebuf, const float* __restrict__ Hmat,
                         const float* __restrict__ bias, float* __restrict__ Out, int Nn) {
    int n = blockIdx.x;
    int h = threadIdx.x >> 5;
    int lane = threadIdx.x & 31;
    const int HC = H * C_;
    int rs = rowptr[n], re = rowptr[n + 1];
    float* ep = ebuf + (size_t)h * ETMAX;

    // pass 1: max (lane-parallel, coalesced)
    float m = -INFINITY;
    for (int i = rs + lane; i < re; i += 32)
        m = fmaxf(m, ep[i]);
#pragma unroll
    for (int o = 16; o; o >>= 1) m = fmaxf(m, __shfl_xor_sync(0xffffffffu, m, o));

    // pass 2: exp in place + sum (coalesced)
    float ssum = 0.f;
    for (int i = rs + lane; i < re; i += 32) {
        float ex = __expf(ep[i] - m);
        ep[i] = ex;
        ssum += ex;
    }
#pragma unroll
    for (int o = 16; o; o >>= 1) ssum += __shfl_xor_sync(0xffffffffu, ssum, o);
    float inv_s = 1.f / ssum;

    // pass 3: serial accumulate (channel-parallel across lanes)
    float acc0 = 0.f, acc1 = 0.f;
#pragma unroll 2
    for (int i = rs; i < re; ++i) {
        int s = csr_src[i];                 // broadcast
        float a = ep[i] * inv_s;            // broadcast, sequential -> L1 hit
        const float* hp = Hmat + (size_t)s * HC + h * C_;
        acc0 += a * hp[lane];
        if (C_ == 64) acc1 += a * hp[lane + 32];
    }
    float* op = Out + (size_t)n * HC + h * C_;
    float v0 = acc0 + bias[h * C_ + lane];
    op[lane] = v0 > 0.f ? v0 : 0.f;
    if (C_ == 64) {
        float v1 = acc1 + bias[h * C_ + lane + 32];
        op[lane + 32] = v1 > 0.f ? v1 : 0.f;
    }
}

// ---------------- final head: out1 = sigmoid(concat(x1,x2,x3) @ Wf + bf) ----------------
__global__ void final_head(const float* __restrict__ x1, const float* __restrict__ x2,
                           const float* __restrict__ x3, const float* __restrict__ Wf,
                           const float* __restrict__ bf, float* __restrict__ out1, int Nn) {
    int warp = (blockIdx.x * blockDim.x + threadIdx.x) >> 5;
    int lane = threadIdx.x & 31;
    if (warp >= Nn) return;
    float acc = 0.f;
    for (int j = lane; j < 256; j += 32) acc += x1[(size_t)warp * 256 + j] * Wf[j];
    for (int j = lane; j < 256; j += 32) acc += x2[(size_t)warp * 256 + j] * Wf[256 + j];
    for (int j = lane; j < 768; j += 32) acc += x3[(size_t)warp * 768 + j] * Wf[512 + j];
#pragma unroll
    for (int o = 16; o; o >>= 1) acc += __shfl_down_sync(0xffffffffu, acc, o);
    if (lane == 0) out1[warp] = sigmoidf_(acc + bf[0]);
}

// ---------------- MLP ----------------
__global__ void mlp1(const float* __restrict__ x, const float* __restrict__ out1,
                     const float* __restrict__ M1w, const float* __restrict__ M1b,
                     float* __restrict__ h1, int Nn) {
    int t = blockIdx.x * blockDim.x + threadIdx.x;
    if (t >= Nn * 128) return;
    int n = t / 128, j = t - n * 128;
    float acc = M1b[j];
    const float* xr = x + n * 16;
#pragma unroll
    for (int k = 0; k < 16; ++k) acc += xr[k] * M1w[k * 128 + j];
    acc += out1[n] * M1w[16 * 128 + j];
    h1[t] = acc > 0.f ? acc : 0.f;
}

__global__ void mlp2(const float* __restrict__ h1, const float* __restrict__ M2w,
                     const float* __restrict__ M2b, float* __restrict__ h2, int Nn) {
    int t = blockIdx.x * blockDim.x + threadIdx.x;
    if (t >= Nn * 64) return;
    int n = t / 64, j = t - n * 64;
    float acc = M2b[j];
    const float* hr = h1 + (size_t)n * 128;
    for (int k = 0; k < 128; ++k) acc += hr[k] * M2w[k * 64 + j];
    h2[t] = acc > 0.f ? acc : 0.f;
}

__global__ void mlp3(const float* __restrict__ h2, const float* __restrict__ M3w,
                     const float* __restrict__ M3b, float* __restrict__ out2, int Nn) {
    int warp = (blockIdx.x * blockDim.x + threadIdx.x) >> 5;
    int lane = threadIdx.x & 31;
    if (warp >= Nn) return;
    float acc = h2[(size_t)warp * 64 + lane] * M3w[lane]
              + h2[(size_t)warp * 64 + lane + 32] * M3w[lane + 32];
#pragma unroll
    for (int o = 16; o; o >>= 1) acc += __shfl_down_sync(0xffffffffu, acc, o);
    if (lane == 0) out2[warp] = sigmoidf_(acc + M3b[0]);
}

// ---------------- host orchestration ----------------
static void run_gat_layer(const float* X, int K,
                          const float* W, const float* a_s, const float* a_d, const float* b,
                          int H, int C, int Nn, int Et,
                          const int* rowptr, const int* csrsrc, const int* csrdst,
                          float* hbuf, float* albuf, float* arbuf, float* ebuf,
                          float* Out) {
    int HC = H * C;
    dim3 gg(cdiv(Nn, 64), HC / 64);
    sgemm64<<<gg, 256>>>(X, W, hbuf, Nn, HC, K);
    alar_kernel<<<cdiv(Nn * H, 256), 256>>>(hbuf, a_s, a_d, albuf, arbuf, Nn, H, C);
    if (H == 8) {
        edge_score_csr<8><<<cdiv(Et, 256), 256>>>(csrsrc, csrdst, Et, albuf, arbuf, ebuf);
        agg_node<8, 32><<<Nn, 256>>>(rowptr, csrsrc, ebuf, hbuf, b, Out, Nn);
    } else {
        edge_score_csr<12><<<cdiv(Et, 256), 256>>>(csrsrc, csrdst, Et, albuf, arbuf, ebuf);
        agg_node<12, 64><<<Nn, 384>>>(rowptr, csrsrc, ebuf, hbuf, b, Out, Nn);
    }
}

extern "C" void kernel_launch(void* const* d_in, const int* in_sizes, int n_in,
                              void* d_out, int out_size) {
    const float* x   = (const float*)d_in[0];
    const int*   ei  = (const int*)  d_in[1];
    const float* W1  = (const float*)d_in[3];
    const float* a1s = (const float*)d_in[4];
    const float* a1d = (const float*)d_in[5];
    const float* b1  = (const float*)d_in[6];
    const float* W2  = (const float*)d_in[7];
    const float* a2s = (const float*)d_in[8];
    const float* a2d = (const float*)d_in[9];
    const float* b2  = (const float*)d_in[10];
    const float* W3  = (const float*)d_in[11];
    const float* a3s = (const float*)d_in[12];
    const float* a3d = (const float*)d_in[13];
    const float* b3  = (const float*)d_in[14];
    const float* Wf  = (const float*)d_in[15];
    const float* bf  = (const float*)d_in[16];
    const float* M1w = (const float*)d_in[17];
    const float* M1b = (const float*)d_in[18];
    const float* M2w = (const float*)d_in[19];
    const float* M2b = (const float*)d_in[20];
    const float* M3w = (const float*)d_in[21];
    const float* M3b = (const float*)d_in[22];

    int Nn = in_sizes[0] / 16;
    int E  = in_sizes[1] / 2;
    int Et = E + Nn;

    float *h_, *x1_, *x2_, *x3_, *al_, *ar_, *e_, *mh1_, *mh2_;
    int *deg_, *rowptr_, *cursor_, *csrsrc_, *csrdst_;
    cudaGetSymbolAddress((void**)&h_,     g_h);
    cudaGetSymbolAddress((void**)&x1_,    g_x1);
    cudaGetSymbolAddress((void**)&x2_,    g_x2);
    cudaGetSymbolAddress((void**)&x3_,    g_x3);
    cudaGetSymbolAddress((void**)&al_,    g_al);
    cudaGetSymbolAddress((void**)&ar_,    g_ar);
    cudaGetSymbolAddress((void**)&e_,     g_e);
    cudaGetSymbolAddress((void**)&mh1_,   g_mh1);
    cudaGetSymbolAddress((void**)&mh2_,   g_mh2);
    cudaGetSymbolAddress((void**)&deg_,   g_deg);
    cudaGetSymbolAddress((void**)&rowptr_,g_rowptr);
    cudaGetSymbolAddress((void**)&cursor_,g_cursor);
    cudaGetSymbolAddress((void**)&csrsrc_,g_csrsrc);
    cudaGetSymbolAddress((void**)&csrdst_,g_csrdst);

    float* out1 = (float*)d_out;        // [N]
    float* out2 = (float*)d_out + Nn;   // [N]

    // ---- build CSR by destination (graph fixed across layers) ----
    zero_int<<<cdiv(Nn, 256), 256>>>(deg_, Nn);
    count_deg<<<cdiv(Et, 256), 256>>>(ei, E, Et, deg_);
    scan_deg<<<1, 256>>>(deg_, rowptr_, cursor_, Nn);
    scatter_csr<<<cdiv(Et, 256), 256>>>(ei, E, Et, cursor_, csrsrc_, csrdst_);

    // ---- GAT layers ----
    run_gat_layer(x,   16,  W1, a1s, a1d, b1, 8, 32,  Nn, Et,
                  rowptr_, csrsrc_, csrdst_, h_, al_, ar_, e_, x1_);
    run_gat_layer(x1_, 256, W2, a2s, a2d, b2, 8, 32,  Nn, Et,
                  rowptr_, csrsrc_, csrdst_, h_, al_, ar_, e_, x2_);
    run_gat_layer(x2_, 256, W3, a3s, a3d, b3, 12, 64, Nn, Et,
                  rowptr_, csrsrc_, csrdst_, h_, al_, ar_, e_, x3_);

    // ---- head ----
    final_head<<<cdiv(Nn * 32, 256), 256>>>(x1_, x2_, x3_, Wf, bf, out1, Nn);

    // ---- MLP ----
    mlp1<<<cdiv(Nn * 128, 256), 256>>>(x, out1, M1w, M1b, mh1_, Nn);
    mlp2<<<cdiv(Nn * 64, 256), 256>>>(mh1_, M2w, M2b, mh2_, Nn);
    mlp3<<<cdiv(Nn * 32, 256), 256>>>(mh2_, M3w, M3b, out2, Nn);
}

// round 7
// speedup vs baseline: 1.3446x; 1.0983x over previous
#include <cuda_runtime.h>
#include <math.h>

// ---------------- scratch (device globals; no allocation at launch) ----------------
#define NMAX 10000
#define EMAX 320000
#define ETMAX (EMAX + NMAX)

__device__ float g_h  [NMAX * 768];
__device__ float g_x1 [NMAX * 256];
__device__ float g_x2 [NMAX * 256];
__device__ float g_x3 [NMAX * 768];
__device__ float g_al [NMAX * 12];
__device__ float g_ar [NMAX * 12];
__device__ float g_e  [12 * ETMAX];   // HEAD-MAJOR: g_e[h*ETMAX + slot]
__device__ float g_px [NMAX * 128];   // mlp1 pre-activation (x-part)
__device__ float g_mh1[NMAX * 128];
__device__ float g_mh2[NMAX * 64];
__device__ float g_wl [256 * 12];     // folded W@a_s  [K,H]
__device__ float g_wr [256 * 12];     // folded W@a_d  [K,H]
__device__ int   g_deg   [NMAX];
__device__ int   g_rowptr[NMAX + 1];
__device__ int   g_cursor[NMAX];
__device__ int   g_csrsrc[ETMAX];
__device__ int   g_csrdst[ETMAX];

__device__ __forceinline__ float sigmoidf_(float x) {
    return 1.f / (1.f + expf(-x));
}

static inline int cdiv(int a, int b) { return (a + b - 1) / b; }

// ---------------- CSR build ----------------
__global__ void zero_int(int* p, int n) {
    int t = blockIdx.x * blockDim.x + threadIdx.x;
    if (t < n) p[t] = 0;
}

__global__ void count_deg(const int* __restrict__ ei, int E, int Et, int* __restrict__ deg) {
    int e = blockIdx.x * blockDim.x + threadIdx.x;
    if (e >= Et) return;
    int d = (e < E) ? ei[E + e] : (e - E);
    atomicAdd(&deg[d], 1);
}

__global__ void scan_deg(const int* __restrict__ deg, int* __restrict__ rowptr,
                         int* __restrict__ cursor, int Nn) {
    __shared__ int part[256];
    __shared__ int partx[256];
    int chunk = (Nn + 255) / 256;
    int begin = threadIdx.x * chunk;
    int end = begin + chunk; if (end > Nn) end = Nn;
    if (begin > Nn) begin = Nn;
    int s = 0;
    for (int i = begin; i < end; ++i) s += deg[i];
    part[threadIdx.x] = s;
    __syncthreads();
    if (threadIdx.x == 0) {
        int run = 0;
        for (int i = 0; i < 256; ++i) { partx[i] = run; run += part[i]; }
    }
    __syncthreads();
    int run = partx[threadIdx.x];
    for (int i = begin; i < end; ++i) {
        rowptr[i] = run; cursor[i] = run;
        run += deg[i];
    }
    if (end == Nn && begin <= Nn) rowptr[Nn] = run;
}

__global__ void scatter_csr(const int* __restrict__ ei, int E, int Et,
                            int* __restrict__ cursor, int* __restrict__ csr_src,
                            int* __restrict__ csr_dst) {
    int e = blockIdx.x * blockDim.x + threadIdx.x;
    if (e >= Et) return;
    int s, d;
    if (e < E) { s = ei[e]; d = ei[E + e]; }
    else       { s = e - E; d = e - E; }
    int pos = atomicAdd(&cursor[d], 1);
    csr_src[pos] = s;
    csr_dst[pos] = d;
}

// ---------------- tiled SGEMM: C[M,N] = A[M,K] @ B[K,N] ----------------
__global__ void sgemm64(const float* __restrict__ A, const float* __restrict__ B,
                        float* __restrict__ Cmat, int M, int N, int K) {
    __shared__ float As[16][68];
    __shared__ float Bs[16][64];
    int t = threadIdx.x;
    int row0 = blockIdx.x * 64;
    int col0 = blockIdx.y * 64;
    int tx = t & 15, ty = t >> 4;
    int ar = t >> 2, ac = (t & 3) * 4;
    int br = t >> 4, bc = (t & 15) * 4;
    float acc[4][4];
#pragma unroll
    for (int i = 0; i < 4; ++i)
#pragma unroll
        for (int j = 0; j < 4; ++j) acc[i][j] = 0.f;

    for (int k0 = 0; k0 < K; k0 += 16) {
        float4 av = make_float4(0.f, 0.f, 0.f, 0.f);
        if (row0 + ar < M)
            av = *(const float4*)(A + (size_t)(row0 + ar) * K + k0 + ac);
        As[ac + 0][ar] = av.x;
        As[ac + 1][ar] = av.y;
        As[ac + 2][ar] = av.z;
        As[ac + 3][ar] = av.w;
        *(float4*)&Bs[br][bc] = *(const float4*)(B + (size_t)(k0 + br) * N + col0 + bc);
        __syncthreads();
#pragma unroll
        for (int k = 0; k < 16; ++k) {
            float4 a4 = *(const float4*)&As[k][ty * 4];
            float4 b4 = *(const float4*)&Bs[k][tx * 4];
            acc[0][0] += a4.x * b4.x; acc[0][1] += a4.x * b4.y;
            acc[0][2] += a4.x * b4.z; acc[0][3] += a4.x * b4.w;
            acc[1][0] += a4.y * b4.x; acc[1][1] += a4.y * b4.y;
            acc[1][2] += a4.y * b4.z; acc[1][3] += a4.y * b4.w;
            acc[2][0] += a4.z * b4.x; acc[2][1] += a4.z * b4.y;
            acc[2][2] += a4.z * b4.z; acc[2][3] += a4.z * b4.w;
            acc[3][0] += a4.w * b4.x; acc[3][1] += a4.w * b4.y;
            acc[3][2] += a4.w * b4.z; acc[3][3] += a4.w * b4.w;
        }
        __syncthreads();
    }
#pragma unroll
    for (int i = 0; i < 4; ++i) {
        int r = row0 + ty * 4 + i;
        if (r < M) {
            float4 v = make_float4(acc[i][0], acc[i][1], acc[i][2], acc[i][3]);
            *(float4*)(Cmat + (size_t)r * N + col0 + tx * 4) = v;
        }
    }
}

// ---------------- fold attention vectors through W: wl/wr[k,h] = sum_c W[k,h*C+c]*a[h,c] ----------------
__global__ void wa_kernel(const float* __restrict__ W, const float* __restrict__ a_s,
                          const float* __restrict__ a_d,
                          float* __restrict__ wl, float* __restrict__ wr,
                          int K, int H, int C) {
    int t = blockIdx.x * blockDim.x + threadIdx.x;
    if (t >= K * H) return;
    int k = t / H, h = t - k * H;
    const float* wrow = W + (size_t)k * H * C + h * C;
    const float* as = a_s + h * C;
    const float* ad = a_d + h * C;
    float sl = 0.f, sr = 0.f;
    for (int c = 0; c < C; ++c) {
        float w = wrow[c];
        sl += w * as[c];
        sr += w * ad[c];
    }
    wl[t] = sl;
    wr[t] = sr;
}

// ---------------- al/ar directly from X: al[n,h] = X[n,:] . wl[:,h] ----------------
__global__ void alar_x(const float* __restrict__ X,
                       const float* __restrict__ wl, const float* __restrict__ wr,
                       float* __restrict__ al, float* __restrict__ ar,
                       int Nn, int K, int H) {
    int t = blockIdx.x * blockDim.x + threadIdx.x;
    if (t >= Nn * H) return;
    int n = t / H, h = t - n * H;
    const float* xr = X + (size_t)n * K;
    float sa = 0.f, sd = 0.f;
    for (int k = 0; k < K; ++k) {
        float xv = xr[k];
        sa += xv * wl[k * H + h];
        sd += xv * wr[k * H + h];
    }
    al[t] = sa;
    ar[t] = sd;
}

// ---------------- per-slot scores for all heads (CSR order, HEAD-MAJOR out) ----------------
template<int H>
__global__ void edge_score_csr(const int* __restrict__ csr_src, const int* __restrict__ csr_dst,
                               int Et,
                               const float* __restrict__ al, const float* __restrict__ ar,
                               float* __restrict__ ebuf) {
    int i = blockIdx.x * blockDim.x + threadIdx.x;
    if (i >= Et) return;
    int s = csr_src[i];
    int d = csr_dst[i];
    const float4* a4 = (const float4*)(al + s * H);
    const float4* r4 = (const float4*)(ar + d * H);
#pragma unroll
    for (int q = 0; q < H / 4; ++q) {
        float4 a = a4[q], r = r4[q];
        float v0 = a.x + r.x; v0 = v0 > 0.f ? v0 : 0.2f * v0;
        float v1 = a.y + r.y; v1 = v1 > 0.f ? v1 : 0.2f * v1;
        float v2 = a.z + r.z; v2 = v2 > 0.f ? v2 : 0.2f * v2;
        float v3 = a.w + r.w; v3 = v3 > 0.f ? v3 : 0.2f * v3;
        ebuf[(size_t)(q * 4 + 0) * ETMAX + i] = v0;
        ebuf[(size_t)(q * 4 + 1) * ETMAX + i] = v1;
        ebuf[(size_t)(q * 4 + 2) * ETMAX + i] = v2;
        ebuf[(size_t)(q * 4 + 3) * ETMAX + i] = v3;
    }
}

// ---------------- block-per-node aggregation: H warps (one per head) ----------------
template<int H, int C_>
__global__ void agg_node(const int* __restrict__ rowptr, const int* __restrict__ csr_src,
                         float* __restrict__ ebuf, const float* __restrict__ Hmat,
                         const float* __restrict__ bias, float* __restrict__ Out, int Nn) {
    int n = blockIdx.x;
    int h = threadIdx.x >> 5;
    int lane = threadIdx.x & 31;
    const int HC = H * C_;
    int rs = rowptr[n], re = rowptr[n + 1];
    float* ep = ebuf + (size_t)h * ETMAX;

    float m = -INFINITY;
    for (int i = rs + lane; i < re; i += 32)
        m = fmaxf(m, ep[i]);
#pragma unroll
    for (int o = 16; o; o >>= 1) m = fmaxf(m, __shfl_xor_sync(0xffffffffu, m, o));

    float ssum = 0.f;
    for (int i = rs + lane; i < re; i += 32) {
        float ex = __expf(ep[i] - m);
        ep[i] = ex;
        ssum += ex;
    }
#pragma unroll
    for (int o = 16; o; o >>= 1) ssum += __shfl_xor_sync(0xffffffffu, ssum, o);
    float inv_s = 1.f / ssum;

    float acc0 = 0.f, acc1 = 0.f;
#pragma unroll 2
    for (int i = rs; i < re; ++i) {
        int s = csr_src[i];
        float a = ep[i] * inv_s;
        const float* hp = Hmat + (size_t)s * HC + h * C_;
        acc0 += a * hp[lane];
        if (C_ == 64) acc1 += a * hp[lane + 32];
    }
    float* op = Out + (size_t)n * HC + h * C_;
    float v0 = acc0 + bias[h * C_ + lane];
    op[lane] = v0 > 0.f ? v0 : 0.f;
    if (C_ == 64) {
        float v1 = acc1 + bias[h * C_ + lane + 32];
        op[lane + 32] = v1 > 0.f ? v1 : 0.f;
    }
}

// ---------------- final head ----------------
__global__ void final_head(const float* __restrict__ x1, const float* __restrict__ x2,
                           const float* __restrict__ x3, const float* __restrict__ Wf,
                           const float* __restrict__ bf, float* __restrict__ out1, int Nn) {
    int warp = (blockIdx.x * blockDim.x + threadIdx.x) >> 5;
    int lane = threadIdx.x & 31;
    if (warp >= Nn) return;
    float acc = 0.f;
    for (int j = lane; j < 256; j += 32) acc += x1[(size_t)warp * 256 + j] * Wf[j];
    for (int j = lane; j < 256; j += 32) acc += x2[(size_t)warp * 256 + j] * Wf[256 + j];
    for (int j = lane; j < 768; j += 32) acc += x3[(size_t)warp * 768 + j] * Wf[512 + j];
#pragma unroll
    for (int o = 16; o; o >>= 1) acc += __shfl_down_sync(0xffffffffu, acc, o);
    if (lane == 0) out1[warp] = sigmoidf_(acc + bf[0]);
}

// ---------------- MLP ----------------
__global__ void mlp1_pre(const float* __restrict__ x,
                         const float* __restrict__ M1w, const float* __restrict__ M1b,
                         float* __restrict__ px, int Nn) {
    int t = blockIdx.x * blockDim.x + threadIdx.x;
    if (t >= Nn * 128) return;
    int n = t / 128, j = t - n * 128;
    float acc = M1b[j];
    const float* xr = x + n * 16;
#pragma unroll
    for (int k = 0; k < 16; ++k) acc += xr[k] * M1w[k * 128 + j];
    px[t] = acc;
}

__global__ void mlp1_post(const float* __restrict__ px, const float* __restrict__ out1,
                          const float* __restrict__ M1w, float* __restrict__ h1, int Nn) {
    int t = blockIdx.x * blockDim.x + threadIdx.x;
    if (t >= Nn * 128) return;
    int n = t / 128, j = t - n * 128;
    float acc = px[t] + out1[n] * M1w[16 * 128 + j];
    h1[t] = acc > 0.f ? acc : 0.f;
}

__global__ void mlp2(const float* __restrict__ h1, const float* __restrict__ M2w,
                     const float* __restrict__ M2b, float* __restrict__ h2, int Nn) {
    int t = blockIdx.x * blockDim.x + threadIdx.x;
    if (t >= Nn * 64) return;
    int n = t / 64, j = t - n * 64;
    float acc = M2b[j];
    const float* hr = h1 + (size_t)n * 128;
    for (int k = 0; k < 128; ++k) acc += hr[k] * M2w[k * 64 + j];
    h2[t] = acc > 0.f ? acc : 0.f;
}

__global__ void mlp3(const float* __restrict__ h2, const float* __restrict__ M3w,
                     const float* __restrict__ M3b, float* __restrict__ out2, int Nn) {
    int warp = (blockIdx.x * blockDim.x + threadIdx.x) >> 5;
    int lane = threadIdx.x & 31;
    if (warp >= Nn) return;
    float acc = h2[(size_t)warp * 64 + lane] * M3w[lane]
              + h2[(size_t)warp * 64 + lane + 32] * M3w[lane + 32];
#pragma unroll
    for (int o = 16; o; o >>= 1) acc += __shfl_down_sync(0xffffffffu, acc, o);
    if (lane == 0) out2[warp] = sigmoidf_(acc + M3b[0]);
}

extern "C" void kernel_launch(void* const* d_in, const int* in_sizes, int n_in,
                              void* d_out, int out_size) {
    const float* x   = (const float*)d_in[0];
    const int*   ei  = (const int*)  d_in[1];
    const float* W1  = (const float*)d_in[3];
    const float* a1s = (const float*)d_in[4];
    const float* a1d = (const float*)d_in[5];
    const float* b1  = (const float*)d_in[6];
    const float* W2  = (const float*)d_in[7];
    const float* a2s = (const float*)d_in[8];
    const float* a2d = (const float*)d_in[9];
    const float* b2  = (const float*)d_in[10];
    const float* W3  = (const float*)d_in[11];
    const float* a3s = (const float*)d_in[12];
    const float* a3d = (const float*)d_in[13];
    const float* b3  = (const float*)d_in[14];
    const float* Wf  = (const float*)d_in[15];
    const float* bf  = (const float*)d_in[16];
    const float* M1w = (const float*)d_in[17];
    const float* M1b = (const float*)d_in[18];
    const float* M2w = (const float*)d_in[19];
    const float* M2b = (const float*)d_in[20];
    const float* M3w = (const float*)d_in[21];
    const float* M3b = (const float*)d_in[22];

    int Nn = in_sizes[0] / 16;
    int E  = in_sizes[1] / 2;
    int Et = E + Nn;

    float *h_, *x1_, *x2_, *x3_, *al_, *ar_, *e_, *px_, *mh1_, *mh2_, *wl_, *wr_;
    int *deg_, *rowptr_, *cursor_, *csrsrc_, *csrdst_;
    cudaGetSymbolAddress((void**)&h_,     g_h);
    cudaGetSymbolAddress((void**)&x1_,    g_x1);
    cudaGetSymbolAddress((void**)&x2_,    g_x2);
    cudaGetSymbolAddress((void**)&x3_,    g_x3);
    cudaGetSymbolAddress((void**)&al_,    g_al);
    cudaGetSymbolAddress((void**)&ar_,    g_ar);
    cudaGetSymbolAddress((void**)&e_,     g_e);
    cudaGetSymbolAddress((void**)&px_,    g_px);
    cudaGetSymbolAddress((void**)&mh1_,   g_mh1);
    cudaGetSymbolAddress((void**)&mh2_,   g_mh2);
    cudaGetSymbolAddress((void**)&wl_,    g_wl);
    cudaGetSymbolAddress((void**)&wr_,    g_wr);
    cudaGetSymbolAddress((void**)&deg_,   g_deg);
    cudaGetSymbolAddress((void**)&rowptr_,g_rowptr);
    cudaGetSymbolAddress((void**)&cursor_,g_cursor);
    cudaGetSymbolAddress((void**)&csrsrc_,g_csrsrc);
    cudaGetSymbolAddress((void**)&csrdst_,g_csrdst);

    float* out1 = (float*)d_out;
    float* out2 = (float*)d_out + Nn;

    // side stream + events (created once; creation is not device-memory allocation)
    static cudaStream_t s1 = nullptr;
    static cudaEvent_t evF[3], evJ[3];
    if (!s1) {
        cudaStreamCreateWithFlags(&s1, cudaStreamNonBlocking);
        for (int i = 0; i < 3; ++i) {
            cudaEventCreateWithFlags(&evF[i], cudaEventDisableTiming);
            cudaEventCreateWithFlags(&evJ[i], cudaEventDisableTiming);
        }
    }
    cudaStream_t s0 = 0;  // legacy default (captured) stream

    // ================= layer 1: fork =================
    cudaEventRecord(evF[0], s0);
    cudaStreamWaitEvent(s1, evF[0], 0);
    // side chain: CSR build + scores(L1) + mlp1 precompute
    zero_int<<<cdiv(Nn, 256), 256, 0, s1>>>(deg_, Nn);
    count_deg<<<cdiv(Et, 256), 256, 0, s1>>>(ei, E, Et, deg_);
    scan_deg<<<1, 256, 0, s1>>>(deg_, rowptr_, cursor_, Nn);
    scatter_csr<<<cdiv(Et, 256), 256, 0, s1>>>(ei, E, Et, cursor_, csrsrc_, csrdst_);
    wa_kernel<<<cdiv(16 * 8, 128), 128, 0, s1>>>(W1, a1s, a1d, wl_, wr_, 16, 8, 32);
    alar_x<<<cdiv(Nn * 8, 256), 256, 0, s1>>>(x, wl_, wr_, al_, ar_, Nn, 16, 8);
    edge_score_csr<8><<<cdiv(Et, 256), 256, 0, s1>>>(csrsrc_, csrdst_, Et, al_, ar_, e_);
    mlp1_pre<<<cdiv(Nn * 128, 256), 256, 0, s1>>>(x, M1w, M1b, px_, Nn);
    cudaEventRecord(evJ[0], s1);
    // main: GEMM1
    {
        dim3 gg(cdiv(Nn, 64), 256 / 64);
        sgemm64<<<gg, 256, 0, s0>>>(x, W1, h_, Nn, 256, 16);
    }
    cudaStreamWaitEvent(s0, evJ[0], 0);
    agg_node<8, 32><<<Nn, 256, 0, s0>>>(rowptr_, csrsrc_, e_, h_, b1, x1_, Nn);

    // ================= layer 2 =================
    cudaEventRecord(evF[1], s0);
    cudaStreamWaitEvent(s1, evF[1], 0);
    wa_kernel<<<cdiv(256 * 8, 128), 128, 0, s1>>>(W2, a2s, a2d, wl_, wr_, 256, 8, 32);
    alar_x<<<cdiv(Nn * 8, 256), 256, 0, s1>>>(x1_, wl_, wr_, al_, ar_, Nn, 256, 8);
    edge_score_csr<8><<<cdiv(Et, 256), 256, 0, s1>>>(csrsrc_, csrdst_, Et, al_, ar_, e_);
    cudaEventRecord(evJ[1], s1);
    {
        dim3 gg(cdiv(Nn, 64), 256 / 64);
        sgemm64<<<gg, 256, 0, s0>>>(x1_, W2, h_, Nn, 256, 256);
    }
    cudaStreamWaitEvent(s0, evJ[1], 0);
    agg_node<8, 32><<<Nn, 256, 0, s0>>>(rowptr_, csrsrc_, e_, h_, b2, x2_, Nn);

    // ================= layer 3 =================
    cudaEventRecord(evF[2], s0);
    cudaStreamWaitEvent(s1, evF[2], 0);
    wa_kernel<<<cdiv(256 * 12, 128), 128, 0, s1>>>(W3, a3s, a3d, wl_, wr_, 256, 12, 64);
    alar_x<<<cdiv(Nn * 12, 256), 256, 0, s1>>>(x2_, wl_, wr_, al_, ar_, Nn, 256, 12);
    edge_score_csr<12><<<cdiv(Et, 256), 256, 0, s1>>>(csrsrc_, csrdst_, Et, al_, ar_, e_);
    cudaEventRecord(evJ[2], s1);
    {
        dim3 gg(cdiv(Nn, 64), 768 / 64);
        sgemm64<<<gg, 256, 0, s0>>>(x2_, W3, h_, Nn, 768, 256);
    }
    cudaStreamWaitEvent(s0, evJ[2], 0);
    agg_node<12, 64><<<Nn, 384, 0, s0>>>(rowptr_, csrsrc_, e_, h_, b3, x3_, Nn);

    // ================= head + MLP =================
    final_head<<<cdiv(Nn * 32, 256), 256, 0, s0>>>(x1_, x2_, x3_, Wf, bf, out1, Nn);
    mlp1_post<<<cdiv(Nn * 128, 256), 256, 0, s0>>>(px_, out1, M1w, mh1_, Nn);
    mlp2<<<cdiv(Nn * 64, 256), 256, 0, s0>>>(mh1_, M2w, M2b, mh2_, Nn);
    mlp3<<<cdiv(Nn * 32, 256), 256, 0, s0>>>(mh2_, M3w, M3b, out2, Nn);
}

// round 8
// speedup vs baseline: 1.3603x; 1.0117x over previous
#include <cuda_runtime.h>
#include <cuda_fp16.h>
#include <math.h>

// ---------------- scratch (device globals; no allocation at launch) ----------------
#define NMAX 10000
#define EMAX 320000
#define ETMAX (EMAX + NMAX)

__device__ __half g_h [NMAX * 768];   // pre-aggregation features (fp16; only agg reads)
__device__ float g_x1 [NMAX * 256];
__device__ float g_x2 [NMAX * 256];
__device__ float g_x3 [NMAX * 768];
__device__ float g_al [NMAX * 12];
__device__ float g_ar [NMAX * 12];
__device__ float g_e  [12 * ETMAX];   // HEAD-MAJOR: g_e[h*ETMAX + slot]
__device__ float g_px [NMAX * 128];   // mlp1 pre-activation (x-part)
__device__ float g_mh1[NMAX * 128];
__device__ float g_mh2[NMAX * 64];
__device__ float g_wl [256 * 12];     // folded W@a_s  [K,H]
__device__ float g_wr [256 * 12];     // folded W@a_d  [K,H]
__device__ int   g_deg   [NMAX];
__device__ int   g_rowptr[NMAX + 1];
__device__ int   g_cursor[NMAX];
__device__ int   g_csrsrc[ETMAX];
__device__ int   g_csrdst[ETMAX];

__device__ __forceinline__ float sigmoidf_(float x) {
    return 1.f / (1.f + expf(-x));
}

static inline int cdiv(int a, int b) { return (a + b - 1) / b; }

// ---------------- CSR build ----------------
__global__ void zero_int(int* p, int n) {
    int t = blockIdx.x * blockDim.x + threadIdx.x;
    if (t < n) p[t] = 0;
}

__global__ void count_deg(const int* __restrict__ ei, int E, int Et, int* __restrict__ deg) {
    int e = blockIdx.x * blockDim.x + threadIdx.x;
    if (e >= Et) return;
    int d = (e < E) ? ei[E + e] : (e - E);
    atomicAdd(&deg[d], 1);
}

__global__ void scan_deg(const int* __restrict__ deg, int* __restrict__ rowptr,
                         int* __restrict__ cursor, int Nn) {
    __shared__ int part[256];
    __shared__ int partx[256];
    int chunk = (Nn + 255) / 256;
    int begin = threadIdx.x * chunk;
    int end = begin + chunk; if (end > Nn) end = Nn;
    if (begin > Nn) begin = Nn;
    int s = 0;
    for (int i = begin; i < end; ++i) s += deg[i];
    part[threadIdx.x] = s;
    __syncthreads();
    if (threadIdx.x == 0) {
        int run = 0;
        for (int i = 0; i < 256; ++i) { partx[i] = run; run += part[i]; }
    }
    __syncthreads();
    int run = partx[threadIdx.x];
    for (int i = begin; i < end; ++i) {
        rowptr[i] = run; cursor[i] = run;
        run += deg[i];
    }
    if (end == Nn && begin <= Nn) rowptr[Nn] = run;
}

__global__ void scatter_csr(const int* __restrict__ ei, int E, int Et,
                            int* __restrict__ cursor, int* __restrict__ csr_src,
                            int* __restrict__ csr_dst) {
    int e = blockIdx.x * blockDim.x + threadIdx.x;
    if (e >= Et) return;
    int s, d;
    if (e < E) { s = ei[e]; d = ei[E + e]; }
    else       { s = e - E; d = e - E; }
    int pos = atomicAdd(&cursor[d], 1);
    csr_src[pos] = s;
    csr_dst[pos] = d;
}

// ---------------- tiled SGEMM: C[M,N] = A[M,K] @ B[K,N], fp16 output ----------------
__global__ void sgemm64h(const float* __restrict__ A, const float* __restrict__ B,
                         __half* __restrict__ Cmat, int M, int N, int K) {
    __shared__ float As[16][68];
    __shared__ float Bs[16][64];
    int t = threadIdx.x;
    int row0 = blockIdx.x * 64;
    int col0 = blockIdx.y * 64;
    int tx = t & 15, ty = t >> 4;
    int ar = t >> 2, ac = (t & 3) * 4;
    int br = t >> 4, bc = (t & 15) * 4;
    float acc[4][4];
#pragma unroll
    for (int i = 0; i < 4; ++i)
#pragma unroll
        for (int j = 0; j < 4; ++j) acc[i][j] = 0.f;

    for (int k0 = 0; k0 < K; k0 += 16) {
        float4 av = make_float4(0.f, 0.f, 0.f, 0.f);
        if (row0 + ar < M)
            av = *(const float4*)(A + (size_t)(row0 + ar) * K + k0 + ac);
        As[ac + 0][ar] = av.x;
        As[ac + 1][ar] = av.y;
        As[ac + 2][ar] = av.z;
        As[ac + 3][ar] = av.w;
        *(float4*)&Bs[br][bc] = *(const float4*)(B + (size_t)(k0 + br) * N + col0 + bc);
        __syncthreads();
#pragma unroll
        for (int k = 0; k < 16; ++k) {
            float4 a4 = *(const float4*)&As[k][ty * 4];
            float4 b4 = *(const float4*)&Bs[k][tx * 4];
            acc[0][0] += a4.x * b4.x; acc[0][1] += a4.x * b4.y;
            acc[0][2] += a4.x * b4.z; acc[0][3] += a4.x * b4.w;
            acc[1][0] += a4.y * b4.x; acc[1][1] += a4.y * b4.y;
            acc[1][2] += a4.y * b4.z; acc[1][3] += a4.y * b4.w;
            acc[2][0] += a4.z * b4.x; acc[2][1] += a4.z * b4.y;
            acc[2][2] += a4.z * b4.z; acc[2][3] += a4.z * b4.w;
            acc[3][0] += a4.w * b4.x; acc[3][1] += a4.w * b4.y;
            acc[3][2] += a4.w * b4.z; acc[3][3] += a4.w * b4.w;
        }
        __syncthreads();
    }
#pragma unroll
    for (int i = 0; i < 4; ++i) {
        int r = row0 + ty * 4 + i;
        if (r < M) {
            __half2 p0 = __halves2half2(__float2half_rn(acc[i][0]), __float2half_rn(acc[i][1]));
            __half2 p1 = __halves2half2(__float2half_rn(acc[i][2]), __float2half_rn(acc[i][3]));
            __half2* cp = (__half2*)(Cmat + (size_t)r * N + col0 + tx * 4);
            cp[0] = p0;
            cp[1] = p1;
        }
    }
}

// ---------------- fold attention vectors through W ----------------
__global__ void wa_kernel(const float* __restrict__ W, const float* __restrict__ a_s,
                          const float* __restrict__ a_d,
                          float* __restrict__ wl, float* __restrict__ wr,
                          int K, int H, int C) {
    int t = blockIdx.x * blockDim.x + threadIdx.x;
    if (t >= K * H) return;
    int k = t / H, h = t - k * H;
    const float* wrow = W + (size_t)k * H * C + h * C;
    const float* as = a_s + h * C;
    const float* ad = a_d + h * C;
    float sl = 0.f, sr = 0.f;
    for (int c = 0; c < C; ++c) {
        float w = wrow[c];
        sl += w * as[c];
        sr += w * ad[c];
    }
    wl[t] = sl;
    wr[t] = sr;
}

// ---------------- al/ar directly from X ----------------
__global__ void alar_x(const float* __restrict__ X,
                       const float* __restrict__ wl, const float* __restrict__ wr,
                       float* __restrict__ al, float* __restrict__ ar,
                       int Nn, int K, int H) {
    int t = blockIdx.x * blockDim.x + threadIdx.x;
    if (t >= Nn * H) return;
    int n = t / H, h = t - n * H;
    const float* xr = X + (size_t)n * K;
    float sa = 0.f, sd = 0.f;
    for (int k = 0; k < K; ++k) {
        float xv = xr[k];
        sa += xv * wl[k * H + h];
        sd += xv * wr[k * H + h];
    }
    al[t] = sa;
    ar[t] = sd;
}

// ---------------- per-slot scores for all heads (CSR order, HEAD-MAJOR out) ----------------
template<int H>
__global__ void edge_score_csr(const int* __restrict__ csr_src, const int* __restrict__ csr_dst,
                               int Et,
                               const float* __restrict__ al, const float* __restrict__ ar,
                               float* __restrict__ ebuf) {
    int i = blockIdx.x * blockDim.x + threadIdx.x;
    if (i >= Et) return;
    int s = csr_src[i];
    int d = csr_dst[i];
    const float4* a4 = (const float4*)(al + s * H);
    const float4* r4 = (const float4*)(ar + d * H);
#pragma unroll
    for (int q = 0; q < H / 4; ++q) {
        float4 a = a4[q], r = r4[q];
        float v0 = a.x + r.x; v0 = v0 > 0.f ? v0 : 0.2f * v0;
        float v1 = a.y + r.y; v1 = v1 > 0.f ? v1 : 0.2f * v1;
        float v2 = a.z + r.z; v2 = v2 > 0.f ? v2 : 0.2f * v2;
        float v3 = a.w + r.w; v3 = v3 > 0.f ? v3 : 0.2f * v3;
        ebuf[(size_t)(q * 4 + 0) * ETMAX + i] = v0;
        ebuf[(size_t)(q * 4 + 1) * ETMAX + i] = v1;
        ebuf[(size_t)(q * 4 + 2) * ETMAX + i] = v2;
        ebuf[(size_t)(q * 4 + 3) * ETMAX + i] = v3;
    }
}

// ---------------- block-per-node aggregation: H warps, fp16 h gather ----------------
template<int H, int C_>
__global__ void agg_node(const int* __restrict__ rowptr, const int* __restrict__ csr_src,
                         float* __restrict__ ebuf, const __half* __restrict__ Hmat,
                         const float* __restrict__ bias, float* __restrict__ Out, int Nn) {
    int n = blockIdx.x;
    int h = threadIdx.x >> 5;
    int lane = threadIdx.x & 31;
    const int HC = H * C_;
    int rs = rowptr[n], re = rowptr[n + 1];
    float* ep = ebuf + (size_t)h * ETMAX;

    float m = -INFINITY;
    for (int i = rs + lane; i < re; i += 32)
        m = fmaxf(m, ep[i]);
#pragma unroll
    for (int o = 16; o; o >>= 1) m = fmaxf(m, __shfl_xor_sync(0xffffffffu, m, o));

    float ssum = 0.f;
    for (int i = rs + lane; i < re; i += 32) {
        float ex = __expf(ep[i] - m);
        ep[i] = ex;
        ssum += ex;
    }
#pragma unroll
    for (int o = 16; o; o >>= 1) ssum += __shfl_xor_sync(0xffffffffu, ssum, o);
    float inv_s = 1.f / ssum;

    float acc0 = 0.f, acc1 = 0.f;
#pragma unroll 2
    for (int i = rs; i < re; ++i) {
        int s = csr_src[i];                 // broadcast
        float a = ep[i] * inv_s;            // broadcast, sequential -> L1 hit
        const __half* hp = Hmat + (size_t)s * HC + h * C_;
        if (C_ == 64) {
            __half2 v = *((const __half2*)hp + lane);   // 2 ch per lane, 128B/warp
            float2 vf = __half22float2(v);
            acc0 += a * vf.x;
            acc1 += a * vf.y;
        } else {
            acc0 += a * __half2float(hp[lane]);         // 64B/warp
        }
    }
    float* op = Out + (size_t)n * HC + h * C_;
    if (C_ == 64) {
        int c = lane * 2;
        float v0 = acc0 + bias[h * C_ + c];
        float v1 = acc1 + bias[h * C_ + c + 1];
        op[c]     = v0 > 0.f ? v0 : 0.f;
        op[c + 1] = v1 > 0.f ? v1 : 0.f;
    } else {
        float v0 = acc0 + bias[h * C_ + lane];
        op[lane] = v0 > 0.f ? v0 : 0.f;
    }
}

// ---------------- final head ----------------
__global__ void final_head(const float* __restrict__ x1, const float* __restrict__ x2,
                           const float* __restrict__ x3, const float* __restrict__ Wf,
                           const float* __restrict__ bf, float* __restrict__ out1, int Nn) {
    int warp = (blockIdx.x * blockDim.x + threadIdx.x) >> 5;
    int lane = threadIdx.x & 31;
    if (warp >= Nn) return;
    float acc = 0.f;
    for (int j = lane; j < 256; j += 32) acc += x1[(size_t)warp * 256 + j] * Wf[j];
    for (int j = lane; j < 256; j += 32) acc += x2[(size_t)warp * 256 + j] * Wf[256 + j];
    for (int j = lane; j < 768; j += 32) acc += x3[(size_t)warp * 768 + j] * Wf[512 + j];
#pragma unroll
    for (int o = 16; o; o >>= 1) acc += __shfl_down_sync(0xffffffffu, acc, o);
    if (lane == 0) out1[warp] = sigmoidf_(acc + bf[0]);
}

// ---------------- MLP ----------------
__global__ void mlp1_pre(const float* __restrict__ x,
                         const float* __restrict__ M1w, const float* __restrict__ M1b,
                         float* __restrict__ px, int Nn) {
    int t = blockIdx.x * blockDim.x + threadIdx.x;
    if (t >= Nn * 128) return;
    int n = t / 128, j = t - n * 128;
    float acc = M1b[j];
    const float* xr = x + n * 16;
#pragma unroll
    for (int k = 0; k < 16; ++k) acc += xr[k] * M1w[k * 128 + j];
    px[t] = acc;
}

__global__ void mlp1_post(const float* __restrict__ px, const float* __restrict__ out1,
                          const float* __restrict__ M1w, float* __restrict__ h1, int Nn) {
    int t = blockIdx.x * blockDim.x + threadIdx.x;
    if (t >= Nn * 128) return;
    int n = t / 128, j = t - n * 128;
    float acc = px[t] + out1[n] * M1w[16 * 128 + j];
    h1[t] = acc > 0.f ? acc : 0.f;
}

__global__ void mlp2(const float* __restrict__ h1, const float* __restrict__ M2w,
                     const float* __restrict__ M2b, float* __restrict__ h2, int Nn) {
    int t = blockIdx.x * blockDim.x + threadIdx.x;
    if (t >= Nn * 64) return;
    int n = t / 64, j = t - n * 64;
    float acc = M2b[j];
    const float* hr = h1 + (size_t)n * 128;
    for (int k = 0; k < 128; ++k) acc += hr[k] * M2w[k * 64 + j];
    h2[t] = acc > 0.f ? acc : 0.f;
}

__global__ void mlp3(const float* __restrict__ h2, const float* __restrict__ M3w,
                     const float* __restrict__ M3b, float* __restrict__ out2, int Nn) {
    int warp = (blockIdx.x * blockDim.x + threadIdx.x) >> 5;
    int lane = threadIdx.x & 31;
    if (warp >= Nn) return;
    float acc = h2[(size_t)warp * 64 + lane] * M3w[lane]
              + h2[(size_t)warp * 64 + lane + 32] * M3w[lane + 32];
#pragma unroll
    for (int o = 16; o; o >>= 1) acc += __shfl_down_sync(0xffffffffu, acc, o);
    if (lane == 0) out2[warp] = sigmoidf_(acc + M3b[0]);
}

extern "C" void kernel_launch(void* const* d_in, const int* in_sizes, int n_in,
                              void* d_out, int out_size) {
    const float* x   = (const float*)d_in[0];
    const int*   ei  = (const int*)  d_in[1];
    const float* W1  = (const float*)d_in[3];
    const float* a1s = (const float*)d_in[4];
    const float* a1d = (const float*)d_in[5];
    const float* b1  = (const float*)d_in[6];
    const float* W2  = (const float*)d_in[7];
    const float* a2s = (const float*)d_in[8];
    const float* a2d = (const float*)d_in[9];
    const float* b2  = (const float*)d_in[10];
    const float* W3  = (const float*)d_in[11];
    const float* a3s = (const float*)d_in[12];
    const float* a3d = (const float*)d_in[13];
    const float* b3  = (const float*)d_in[14];
    const float* Wf  = (const float*)d_in[15];
    const float* bf  = (const float*)d_in[16];
    const float* M1w = (const float*)d_in[17];
    const float* M1b = (const float*)d_in[18];
    const float* M2w = (const float*)d_in[19];
    const float* M2b = (const float*)d_in[20];
    const float* M3w = (const float*)d_in[21];
    const float* M3b = (const float*)d_in[22];

    int Nn = in_sizes[0] / 16;
    int E  = in_sizes[1] / 2;
    int Et = E + Nn;

    __half* h_;
    float *x1_, *x2_, *x3_, *al_, *ar_, *e_, *px_, *mh1_, *mh2_, *wl_, *wr_;
    int *deg_, *rowptr_, *cursor_, *csrsrc_, *csrdst_;
    cudaGetSymbolAddress((void**)&h_,     g_h);
    cudaGetSymbolAddress((void**)&x1_,    g_x1);
    cudaGetSymbolAddress((void**)&x2_,    g_x2);
    cudaGetSymbolAddress((void**)&x3_,    g_x3);
    cudaGetSymbolAddress((void**)&al_,    g_al);
    cudaGetSymbolAddress((void**)&ar_,    g_ar);
    cudaGetSymbolAddress((void**)&e_,     g_e);
    cudaGetSymbolAddress((void**)&px_,    g_px);
    cudaGetSymbolAddress((void**)&mh1_,   g_mh1);
    cudaGetSymbolAddress((void**)&mh2_,   g_mh2);
    cudaGetSymbolAddress((void**)&wl_,    g_wl);
    cudaGetSymbolAddress((void**)&wr_,    g_wr);
    cudaGetSymbolAddress((void**)&deg_,   g_deg);
    cudaGetSymbolAddress((void**)&rowptr_,g_rowptr);
    cudaGetSymbolAddress((void**)&cursor_,g_cursor);
    cudaGetSymbolAddress((void**)&csrsrc_,g_csrsrc);
    cudaGetSymbolAddress((void**)&csrdst_,g_csrdst);

    float* out1 = (float*)d_out;
    float* out2 = (float*)d_out + Nn;

    static cudaStream_t s1 = nullptr;
    static cudaEvent_t evF[3], evJ[3];
    if (!s1) {
        cudaStreamCreateWithFlags(&s1, cudaStreamNonBlocking);
        for (int i = 0; i < 3; ++i) {
            cudaEventCreateWithFlags(&evF[i], cudaEventDisableTiming);
            cudaEventCreateWithFlags(&evJ[i], cudaEventDisableTiming);
        }
    }
    cudaStream_t s0 = 0;

    // ================= layer 1: fork =================
    cudaEventRecord(evF[0], s0);
    cudaStreamWaitEvent(s1, evF[0], 0);
    zero_int<<<cdiv(Nn, 256), 256, 0, s1>>>(deg_, Nn);
    count_deg<<<cdiv(Et, 256), 256, 0, s1>>>(ei, E, Et, deg_);
    scan_deg<<<1, 256, 0, s1>>>(deg_, rowptr_, cursor_, Nn);
    scatter_csr<<<cdiv(Et, 256), 256, 0, s1>>>(ei, E, Et, cursor_, csrsrc_, csrdst_);
    wa_kernel<<<cdiv(16 * 8, 128), 128, 0, s1>>>(W1, a1s, a1d, wl_, wr_, 16, 8, 32);
    alar_x<<<cdiv(Nn * 8, 256), 256, 0, s1>>>(x, wl_, wr_, al_, ar_, Nn, 16, 8);
    edge_score_csr<8><<<cdiv(Et, 256), 256, 0, s1>>>(csrsrc_, csrdst_, Et, al_, ar_, e_);
    mlp1_pre<<<cdiv(Nn * 128, 256), 256, 0, s1>>>(x, M1w, M1b, px_, Nn);
    cudaEventRecord(evJ[0], s1);
    {
        dim3 gg(cdiv(Nn, 64), 256 / 64);
        sgemm64h<<<gg, 256, 0, s0>>>(x, W1, h_, Nn, 256, 16);
    }
    cudaStreamWaitEvent(s0, evJ[0], 0);
    agg_node<8, 32><<<Nn, 256, 0, s0>>>(rowptr_, csrsrc_, e_, h_, b1, x1_, Nn);

    // ================= layer 2 =================
    cudaEventRecord(evF[1], s0);
    cudaStreamWaitEvent(s1, evF[1], 0);
    wa_kernel<<<cdiv(256 * 8, 128), 128, 0, s1>>>(W2, a2s, a2d, wl_, wr_, 256, 8, 32);
    alar_x<<<cdiv(Nn * 8, 256), 256, 0, s1>>>(x1_, wl_, wr_, al_, ar_, Nn, 256, 8);
    edge_score_csr<8><<<cdiv(Et, 256), 256, 0, s1>>>(csrsrc_, csrdst_, Et, al_, ar_, e_);
    cudaEventRecord(evJ[1], s1);
    {
        dim3 gg(cdiv(Nn, 64), 256 / 64);
        sgemm64h<<<gg, 256, 0, s0>>>(x1_, W2, h_, Nn, 256, 256);
    }
    cudaStreamWaitEvent(s0, evJ[1], 0);
    agg_node<8, 32><<<Nn, 256, 0, s0>>>(rowptr_, csrsrc_, e_, h_, b2, x2_, Nn);

    // ================= layer 3 =================
    cudaEventRecord(evF[2], s0);
    cudaStreamWaitEvent(s1, evF[2], 0);
    wa_kernel<<<cdiv(256 * 12, 128), 128, 0, s1>>>(W3, a3s, a3d, wl_, wr_, 256, 12, 64);
    alar_x<<<cdiv(Nn * 12, 256), 256, 0, s1>>>(x2_, wl_, wr_, al_, ar_, Nn, 256, 12);
    edge_score_csr<12><<<cdiv(Et, 256), 256, 0, s1>>>(csrsrc_, csrdst_, Et, al_, ar_, e_);
    cudaEventRecord(evJ[2], s1);
    {
        dim3 gg(cdiv(Nn, 64), 768 / 64);
        sgemm64h<<<gg, 256, 0, s0>>>(x2_, W3, h_, Nn, 768, 256);
    }
    cudaStreamWaitEvent(s0, evJ[2], 0);
    agg_node<12, 64><<<Nn, 384, 0, s0>>>(rowptr_, csrsrc_, e_, h_, b3, x3_, Nn);

    // ================= head + MLP =================
    final_head<<<cdiv(Nn * 32, 256), 256, 0, s0>>>(x1_, x2_, x3_, Wf, bf, out1, Nn);
    mlp1_post<<<cdiv(Nn * 128, 256), 256, 0, s0>>>(px_, out1, M1w, mh1_, Nn);
    mlp2<<<cdiv(Nn * 64, 256), 256, 0, s0>>>(mh1_, M2w, M2b, mh2_, Nn);
    mlp3<<<cdiv(Nn * 32, 256), 256, 0, s0>>>(mh2_, M3w, M3b, out2, Nn);
}